// round 6
// baseline (speedup 1.0000x reference)
#include <cuda_runtime.h>
#include <cuda_bf16.h>
#include <math.h>
#include <stdint.h>

// Problem dims (fixed)
#define BB 2
#define SS 2048
#define DD 1024
#define HH 16
#define DHH 64
#define FF 4096
#define NTOK (BB*SS)   // 4096

// ---------------- scratch (device globals) -----------------------------------
// int8 activation operands + per-row scales
__device__ int8_t g_h8h [NTOK*DD], g_h8l [NTOK*DD];   __device__ float g_Sh [NTOK];
__device__ int8_t g_o8h [NTOK*DD], g_o8l [NTOK*DD];   __device__ float g_So [NTOK];
__device__ int8_t g_h28h[NTOK*DD], g_h28l[NTOK*DD];   __device__ float g_Sh2[NTOK];
__device__ int8_t g_a8h [NTOK*FF], g_a8l [NTOK*FF];   __device__ float g_Sa2[NTOK];
// bf16 pairs for attention path
__device__ __nv_bfloat16 g_q_hi[NTOK*DD], g_q_lo[NTOK*DD];
__device__ __nv_bfloat16 g_k_hi[NTOK*DD], g_k_lo[NTOK*DD];
__device__ __nv_bfloat16 g_v_hi[NTOK*DD], g_v_lo[NTOK*DD];
__device__ __nv_bfloat16 g_o_hi[NTOK*DD], g_o_lo[NTOK*DD];
__device__ __nv_bfloat16 g_act_hi[NTOK*FF], g_act_lo[NTOK*FF];
__device__ float g_add1[NTOK*DD];
// int8 weights [N,K] + per-out-col scales
__device__ int8_t g_wqkv8h[3*DD*DD], g_wqkv8l[3*DD*DD];  __device__ float g_SBqkv[3*DD];
__device__ int8_t g_wo8h[DD*DD],   g_wo8l[DD*DD];        __device__ float g_SBo[DD];
__device__ int8_t g_w18h[FF*DD],   g_w18l[FF*DD];        __device__ float g_SB1[FF];
__device__ int8_t g_w28h[DD*FF],   g_w28l[DD*FF];        __device__ float g_SB2[DD];

// ---------------- helpers ------------------------------------------------------
__device__ __forceinline__ uint32_t smem_u32(const void* p) {
    uint32_t a;
    asm("{ .reg .u64 t; cvta.to.shared.u64 t, %1; cvt.u32.u64 %0, t; }" : "=r"(a) : "l"(p));
    return a;
}
__device__ __forceinline__ void cp_async16(uint32_t dst, const void* src) {
    asm volatile("cp.async.cg.shared.global [%0], [%1], 16;"
                 :: "r"(dst), "l"(src) : "memory");
}
__device__ __forceinline__ void cp_commit() {
    asm volatile("cp.async.commit_group;" ::: "memory");
}
template<int N>
__device__ __forceinline__ void cp_wait() {
    asm volatile("cp.async.wait_group %0;" :: "n"(N) : "memory");
}
__device__ __forceinline__ void ldsm_x4(uint32_t* r, uint32_t addr) {
    asm volatile("ldmatrix.sync.aligned.m8n8.x4.shared.b16 {%0,%1,%2,%3}, [%4];"
                 : "=r"(r[0]), "=r"(r[1]), "=r"(r[2]), "=r"(r[3]) : "r"(addr));
}
__device__ __forceinline__ void ldsm_x4_t(uint32_t* r, uint32_t addr) {
    asm volatile("ldmatrix.sync.aligned.m8n8.x4.trans.shared.b16 {%0,%1,%2,%3}, [%4];"
                 : "=r"(r[0]), "=r"(r[1]), "=r"(r[2]), "=r"(r[3]) : "r"(addr));
}
__device__ __forceinline__ void mma16816(float* d, const uint32_t* a, const uint32_t* b) {
    asm volatile(
        "mma.sync.aligned.m16n8k16.row.col.f32.bf16.bf16.f32 "
        "{%0,%1,%2,%3}, {%4,%5,%6,%7}, {%8,%9}, {%0,%1,%2,%3};"
        : "+f"(d[0]), "+f"(d[1]), "+f"(d[2]), "+f"(d[3])
        : "r"(a[0]), "r"(a[1]), "r"(a[2]), "r"(a[3]), "r"(b[0]), "r"(b[1]));
}
__device__ __forceinline__ void imma16832(int* d, const uint32_t* a, const uint32_t* b) {
    asm volatile(
        "mma.sync.aligned.m16n8k32.row.col.s32.s8.s8.s32 "
        "{%0,%1,%2,%3}, {%4,%5,%6,%7}, {%8,%9}, {%0,%1,%2,%3};"
        : "+r"(d[0]), "+r"(d[1]), "+r"(d[2]), "+r"(d[3])
        : "r"(a[0]), "r"(a[1]), "r"(a[2]), "r"(a[3]), "r"(b[0]), "r"(b[1]));
}
__device__ __forceinline__ uint32_t packbf(float a, float b) {
    __nv_bfloat162 t = __floats2bfloat162_rn(a, b);
    return *reinterpret_cast<uint32_t*>(&t);
}
__device__ __forceinline__ float bfres(float a) {
    __nv_bfloat16 h = __float2bfloat16(a);
    return a - __bfloat162float(h);
}
// quantize fp32 -> (hi,lo) int8 given scale = 16256/rowmax
__device__ __forceinline__ void quant2(float v, float scale, int8_t& qh, int8_t& ql) {
    int qi = __float2int_rn(v * scale);
    int ah = (qi + 64) >> 7;
    qh = (int8_t)ah;
    ql = (int8_t)(qi - (ah << 7));
}

// ---------------- LayerNorm -> int8 hi/lo quant --------------------------------
__global__ void ln_quant_kernel(const float* __restrict__ x,
                                const float* __restrict__ g,
                                const float* __restrict__ b,
                                int8_t* __restrict__ qh, int8_t* __restrict__ ql,
                                float* __restrict__ S) {
    const int row = blockIdx.x;
    const int tid = threadIdx.x;   // 256
    const float* xr = x + (size_t)row * DD;

    float v[4];
    float s = 0.f, s2 = 0.f;
#pragma unroll
    for (int i = 0; i < 4; ++i) {
        v[i] = xr[tid + i * 256];
        s += v[i]; s2 += v[i] * v[i];
    }
    for (int off = 16; off > 0; off >>= 1) {
        s  += __shfl_down_sync(0xffffffffu, s,  off);
        s2 += __shfl_down_sync(0xffffffffu, s2, off);
    }
    __shared__ float rs[8], rs2[8], rmx[8];
    if ((tid & 31) == 0) { rs[tid >> 5] = s; rs2[tid >> 5] = s2; }
    __syncthreads();
    if (tid < 8) { s = rs[tid]; s2 = rs2[tid]; } else { s = 0.f; s2 = 0.f; }
    if (tid < 32) {
        for (int off = 4; off > 0; off >>= 1) {
            s  += __shfl_down_sync(0xffffffffu, s,  off);
            s2 += __shfl_down_sync(0xffffffffu, s2, off);
        }
        if (tid == 0) { rs[0] = s; rs2[0] = s2; }
    }
    __syncthreads();
    const float mean = rs[0] * (1.0f / DD);
    const float var  = rs2[0] * (1.0f / DD) - mean * mean;
    const float inv  = rsqrtf(var + 1e-5f);

    float o[4];
    float mx = 0.f;
#pragma unroll
    for (int i = 0; i < 4; ++i) {
        const int c = tid + i * 256;
        o[i] = (v[i] - mean) * inv * g[c] + b[c];
        mx = fmaxf(mx, fabsf(o[i]));
    }
    for (int off = 16; off > 0; off >>= 1)
        mx = fmaxf(mx, __shfl_down_sync(0xffffffffu, mx, off));
    if ((tid & 31) == 0) rmx[tid >> 5] = mx;
    __syncthreads();
    if (tid < 32) {
        mx = (tid < 8) ? rmx[tid] : 0.f;
        for (int off = 4; off > 0; off >>= 1)
            mx = fmaxf(mx, __shfl_down_sync(0xffffffffu, mx, off));
        if (tid == 0) { rmx[0] = fmaxf(mx, 1e-30f); if (true) S[row] = rmx[0]; }
    }
    __syncthreads();
    const float scale = 16256.f / rmx[0];
    int8_t* qhr = qh + (size_t)row * DD;
    int8_t* qlr = ql + (size_t)row * DD;
#pragma unroll
    for (int i = 0; i < 4; ++i) {
        const int c = tid + i * 256;
        quant2(o[i], scale, qhr[c], qlr[c]);
    }
}

// ---------------- activation (bf16 pair) -> int8 hi/lo quant -------------------
__global__ void aquant_kernel(const __nv_bfloat16* __restrict__ hi,
                              const __nv_bfloat16* __restrict__ lo,
                              int8_t* __restrict__ qh, int8_t* __restrict__ ql,
                              float* __restrict__ S, int K) {
    const int row = blockIdx.x;
    const int tid = threadIdx.x;   // 256
    const int nel = K >> 8;        // 4 or 16
    const __nv_bfloat16* hr = hi + (size_t)row * K;
    const __nv_bfloat16* lr = lo + (size_t)row * K;
    float v[16];
    float mx = 0.f;
    for (int i = 0; i < nel; ++i) {
        const int c = tid + i * 256;
        v[i] = __bfloat162float(hr[c]) + __bfloat162float(lr[c]);
        mx = fmaxf(mx, fabsf(v[i]));
    }
    for (int off = 16; off > 0; off >>= 1)
        mx = fmaxf(mx, __shfl_down_sync(0xffffffffu, mx, off));
    __shared__ float rmx[8];
    if ((tid & 31) == 0) rmx[tid >> 5] = mx;
    __syncthreads();
    if (tid < 32) {
        mx = (tid < 8) ? rmx[tid] : 0.f;
        for (int off = 4; off > 0; off >>= 1)
            mx = fmaxf(mx, __shfl_down_sync(0xffffffffu, mx, off));
        if (tid == 0) { rmx[0] = fmaxf(mx, 1e-30f); S[row] = rmx[0]; }
    }
    __syncthreads();
    const float scale = 16256.f / rmx[0];
    int8_t* qhr = qh + (size_t)row * K;
    int8_t* qlr = ql + (size_t)row * K;
    for (int i = 0; i < nel; ++i) {
        const int c = tid + i * 256;
        quant2(v[i], scale, qhr[c], qlr[c]);
    }
}

// ---------------- weight quant: w[K,N] fp32 -> [N,K] int8 hi/lo + colmax -------
__global__ void wquant_kernel(const float* __restrict__ w,
                              int8_t* __restrict__ qh, int8_t* __restrict__ ql,
                              float* __restrict__ S, int K, int N) {
    __shared__ float red[8][32];
    __shared__ float cmax[32];
    __shared__ float t[32][33];
    const int n0 = blockIdx.x * 32;
    const int tx = threadIdx.x & 31;
    const int ty = threadIdx.x >> 5;   // 0..7
    const int n = n0 + tx;

    float m = 0.f;
    for (int k = ty; k < K; k += 8)
        m = fmaxf(m, fabsf(w[(size_t)k * N + n]));
    red[ty][tx] = m;
    __syncthreads();
    if (ty == 0) {
        float mm = red[0][tx];
#pragma unroll
        for (int j = 1; j < 8; ++j) mm = fmaxf(mm, red[j][tx]);
        mm = fmaxf(mm, 1e-30f);
        cmax[tx] = mm;
        S[n] = mm;
    }
    __syncthreads();

    for (int k0 = 0; k0 < K; k0 += 32) {
#pragma unroll
        for (int i = 0; i < 4; ++i)
            t[ty + 8 * i][tx] = w[(size_t)(k0 + ty + 8 * i) * N + n];
        __syncthreads();
#pragma unroll
        for (int i = 0; i < 4; ++i) {
            const int nl = ty + 8 * i;
            const float sc = 16256.f / cmax[nl];
            int8_t a, b;
            quant2(t[tx][nl], sc, a, b);
            qh[(size_t)(n0 + nl) * K + k0 + tx] = a;
            ql[(size_t)(n0 + nl) * K + k0 + tx] = b;
        }
        __syncthreads();
    }
}

// ---------------- int8 IMMA GEMM: C[M,N] = A[M,K] @ B^T ([N,K] int8) -----------
// 15-bit fixed point: q = ah*128+al; qa*qb ~ 16384*HH + 128*M (al*bl dropped).
// CTA 128x128, BK=64, 8 warps (4x2), warp tile 32x64, 3-stage cp.async.
#define IROWB 80
#define ITILE (128*IROWB)      // 10240
#define IBUF  (4*ITILE)        // 40960 (Ah, Al, Bh, Bl)
#define IGEMM_SMEM (3*IBUF + 1024)

__device__ __forceinline__ void issue_chunk_i8(const int8_t* const* tp, int k0,
                                               uint32_t buf, int tid, int K) {
#pragma unroll
    for (int t = 0; t < 4; ++t) {
#pragma unroll
        for (int u = 0; u < 2; ++u) {
            const int lin = tid + u * 256;       // 0..511
            const int r = lin >> 2;              // 0..127
            const int c4 = lin & 3;              // 16B chunk (64B row)
            const void* src = tp[t] + (size_t)r * K + k0 + c4 * 16;
            cp_async16(buf + t * ITILE + r * IROWB + c4 * 16, src);
        }
    }
    cp_commit();
}

template<int OUTMODE /*0=f32, 1=bf16 pair*/, bool HAS_RES, bool DO_GELU, bool SPLIT3>
__global__ void __launch_bounds__(256)
i8_gemm(const int8_t* __restrict__ A8h, const int8_t* __restrict__ A8l,
        const int8_t* __restrict__ B8h, const int8_t* __restrict__ B8l,
        const float* __restrict__ Sa, const float* __restrict__ Sb,
        const float* __restrict__ bias, const float* __restrict__ bias1,
        const float* __restrict__ bias2,
        const float* __restrict__ res,
        float* __restrict__ Cf,
        __nv_bfloat16* __restrict__ Chi,  __nv_bfloat16* __restrict__ Clo,
        __nv_bfloat16* __restrict__ Chi1, __nv_bfloat16* __restrict__ Clo1,
        __nv_bfloat16* __restrict__ Chi2, __nv_bfloat16* __restrict__ Clo2,
        int M, int N, int K) {
    extern __shared__ char smem[];
    const uint32_t sbase = smem_u32(smem);
    float* bias_s = (float*)(smem + 3 * IBUF);
    float* sb_s   = bias_s + 128;

    const int tid  = threadIdx.x;
    const int wid  = tid >> 5;
    const int lane = tid & 31;
    const int wm = wid >> 1;
    const int wn = wid & 1;
    const int bx = blockIdx.x, by = blockIdx.y;

    const float* bp = bias;
    __nv_bfloat16* chp = Chi;
    __nv_bfloat16* clp = Clo;
    int nout = N;
    int ncol0 = bx * 128;
    if (SPLIT3) {
        const int seg = bx >> 3;
        bp  = (seg == 0) ? bias : (seg == 1) ? bias1 : bias2;
        chp = (seg == 0) ? Chi  : (seg == 1) ? Chi1  : Chi2;
        clp = (seg == 0) ? Clo  : (seg == 1) ? Clo1  : Clo2;
        nout = DD;
        ncol0 = (bx & 7) * 128;
    }
    if (tid < 128) {
        bias_s[tid] = bp[ncol0 + tid];
        sb_s[tid]   = Sb[bx * 128 + tid];
    }

    const size_t aoff = (size_t)by * 128 * K;
    const size_t boff = (size_t)bx * 128 * K;
    const int8_t* tp[4] = { A8h + aoff, A8l + aoff, B8h + boff, B8l + boff };

    const int nchunk = K >> 6;   // BK=64

    int accH[2][8][4], accM[2][8][4];
#pragma unroll
    for (int mt = 0; mt < 2; ++mt)
#pragma unroll
        for (int nt = 0; nt < 8; ++nt)
#pragma unroll
            for (int e = 0; e < 4; ++e) { accH[mt][nt][e] = 0; accM[mt][nt][e] = 0; }

    // ldmatrix per-thread offsets (b16 view of int8 data)
    const int a_row = wm * 32 + (lane & 15);
    const int a_sel = (lane >> 4) * 16;
    const int b_row = wn * 64 + (lane & 7) + ((lane >> 4) << 3);
    const int b_sel = ((lane >> 3) & 1) * 16;

    issue_chunk_i8(tp, 0, sbase, tid, K);
    issue_chunk_i8(tp, 64, sbase + IBUF, tid, K);

    for (int i = 0; i < nchunk; ++i) {
        if (i + 2 < nchunk) {
            issue_chunk_i8(tp, (i + 2) << 6, sbase + ((i + 2) % 3) * IBUF, tid, K);
            cp_wait<2>();
        } else if (i + 1 < nchunk) {
            cp_wait<1>();
        } else {
            cp_wait<0>();
        }
        __syncthreads();

        const uint32_t buf = sbase + (i % 3) * IBUF;
        const uint32_t aAh = buf + a_row * IROWB + a_sel;
        const uint32_t aAl = aAh + ITILE;
        const uint32_t aBh = buf + 2 * ITILE + b_row * IROWB + b_sel;
        const uint32_t aBl = aBh + ITILE;

#pragma unroll
        for (int ks = 0; ks < 2; ++ks) {
            const int ko = ks * 32;   // 32 int8 = 32 bytes
            uint32_t ah[2][4], al[2][4];
#pragma unroll
            for (int mt = 0; mt < 2; ++mt) {
                ldsm_x4(ah[mt], aAh + mt * 16 * IROWB + ko);
                ldsm_x4(al[mt], aAl + mt * 16 * IROWB + ko);
            }
#pragma unroll
            for (int p = 0; p < 4; ++p) {
                uint32_t rh[4], rl[4];
                ldsm_x4(rh, aBh + p * 16 * IROWB + ko);
                ldsm_x4(rl, aBl + p * 16 * IROWB + ko);
#pragma unroll
                for (int mt = 0; mt < 2; ++mt) {
                    imma16832(accH[mt][2*p],   ah[mt], rh);
                    imma16832(accM[mt][2*p],   ah[mt], rl);
                    imma16832(accM[mt][2*p],   al[mt], rh);
                    imma16832(accH[mt][2*p+1], ah[mt], rh + 2);
                    imma16832(accM[mt][2*p+1], ah[mt], rl + 2);
                    imma16832(accM[mt][2*p+1], al[mt], rh + 2);
                }
            }
        }
        __syncthreads();
    }

    // ---------------- epilogue ----------------
    const float C0 = 128.0f / (16256.0f * 16256.0f);
    const int mbase = by * 128 + wm * 32;
    const int nloc0 = wn * 64;
#pragma unroll
    for (int mt = 0; mt < 2; ++mt) {
#pragma unroll
        for (int half = 0; half < 2; ++half) {
            const int m = mbase + mt * 16 + (lane >> 2) + half * 8;
            const float sa = Sa[m] * C0;
#pragma unroll
            for (int nt = 0; nt < 8; ++nt) {
                const int nloc = nloc0 + nt * 8 + 2 * (lane & 3);
                const int n = ncol0 + nloc;
                const float s0 = sa * sb_s[nloc];
                const float s1 = sa * sb_s[nloc + 1];
                float v0 = fmaf(128.f, (float)accH[mt][nt][half*2+0], (float)accM[mt][nt][half*2+0]) * s0 + bias_s[nloc];
                float v1 = fmaf(128.f, (float)accH[mt][nt][half*2+1], (float)accM[mt][nt][half*2+1]) * s1 + bias_s[nloc+1];
                if (DO_GELU) {
                    v0 = 0.5f * v0 * (1.0f + erff(v0 * 0.70710678118654752f));
                    v1 = 0.5f * v1 * (1.0f + erff(v1 * 0.70710678118654752f));
                }
                if (HAS_RES) {
                    const float2 rv = *(const float2*)(res + (size_t)m * nout + n);
                    v0 += rv.x; v1 += rv.y;
                }
                if (OUTMODE == 0) {
                    *(float2*)(Cf + (size_t)m * nout + n) = make_float2(v0, v1);
                } else {
                    __nv_bfloat16 h0 = __float2bfloat16(v0);
                    __nv_bfloat16 h1 = __float2bfloat16(v1);
                    __nv_bfloat16 l0 = __float2bfloat16(v0 - __bfloat162float(h0));
                    __nv_bfloat16 l1 = __float2bfloat16(v1 - __bfloat162float(h1));
                    *(__nv_bfloat162*)(chp + (size_t)m * nout + n) = __halves2bfloat162(h0, h1);
                    *(__nv_bfloat162*)(clp + (size_t)m * nout + n) = __halves2bfloat162(l0, l1);
                }
            }
        }
    }
}

// ---------------- Flash attention via mma.sync (bf16x3, causal) -----------------
#define AROWB 144
#define ATT_SMEM (128*AROWB*2 + 64*AROWB*4)

__global__ void __launch_bounds__(256, 2)
attn_mma(const __nv_bfloat16* __restrict__ qhi, const __nv_bfloat16* __restrict__ qlo,
         const __nv_bfloat16* __restrict__ khi, const __nv_bfloat16* __restrict__ klo,
         const __nv_bfloat16* __restrict__ vhi, const __nv_bfloat16* __restrict__ vlo,
         __nv_bfloat16* __restrict__ ohi, __nv_bfloat16* __restrict__ olo) {
    extern __shared__ char sm[];
    const uint32_t sb  = smem_u32(sm);
    const uint32_t sQh = sb;
    const uint32_t sQl = sb + 128 * AROWB;
    const uint32_t sKh = sb + 256 * AROWB;
    const uint32_t sKl = sKh + 64 * AROWB;
    const uint32_t sVh = sKl + 64 * AROWB;
    const uint32_t sVl = sVh + 64 * AROWB;

    const int qt = gridDim.x - 1 - blockIdx.x;
    const int bh = blockIdx.y;
    const int b = bh >> 4, h = bh & 15;
    const size_t base = (size_t)b * SS * DD + (size_t)h * DHH;
    const int q0 = qt * 128;

    const int tid = threadIdx.x, warp = tid >> 5, lane = tid & 31;

#pragma unroll
    for (int u = 0; u < 4; ++u) {
        const int lin = tid + u * 256;
        const int r = lin >> 3, c = lin & 7;
        const size_t go = base + (size_t)(q0 + r) * DD + c * 8;
        cp_async16(sQh + r * AROWB + c * 16, qhi + go);
        cp_async16(sQl + r * AROWB + c * 16, qlo + go);
    }
    cp_commit();

    float sfr[8][4], oac[8][4];
    float m0 = -1e30f, m1 = -1e30f, l0 = 0.f, l1 = 0.f;
#pragma unroll
    for (int j = 0; j < 8; ++j)
#pragma unroll
        for (int e = 0; e < 4; ++e) oac[j][e] = 0.f;

    const uint32_t qbh = sQh + (warp * 16 + (lane & 15)) * AROWB + (((lane >> 4) << 3) << 1);
    const uint32_t qbl = qbh + 128 * AROWB;
    const int krow = (lane & 7) + ((lane >> 4) << 3);
    const uint32_t kof = (((lane >> 3) & 1) << 3) << 1;
    const int vrow = lane & 15;
    const uint32_t vof = (((lane >> 4) << 3)) << 1;

    cp_wait<0>();
    __syncthreads();

    const int ntile = qt * 2 + 2;
    for (int kt = 0; kt < ntile; ++kt) {
        const int k0 = kt * 64;
        __syncthreads();
        {
            const __nv_bfloat16* src0 = khi + base + (size_t)k0 * DD;
            const __nv_bfloat16* src1 = klo + base + (size_t)k0 * DD;
            const __nv_bfloat16* src2 = vhi + base + (size_t)k0 * DD;
            const __nv_bfloat16* src3 = vlo + base + (size_t)k0 * DD;
#pragma unroll
            for (int u = 0; u < 2; ++u) {
                const int lin = tid + u * 256;
                const int rr = lin >> 3, cc = lin & 7;
                const size_t go = (size_t)rr * DD + cc * 8;
                const uint32_t so = rr * AROWB + cc * 16;
                cp_async16(sKh + so, src0 + go);
                cp_async16(sKl + so, src1 + go);
                cp_async16(sVh + so, src2 + go);
                cp_async16(sVl + so, src3 + go);
            }
            cp_commit(); cp_wait<0>();
            __syncthreads();
        }

#pragma unroll
        for (int j = 0; j < 8; ++j)
#pragma unroll
            for (int e = 0; e < 4; ++e) sfr[j][e] = 0.f;
#pragma unroll
        for (int t = 0; t < 4; ++t) {
            uint32_t qah[4], qal[4];
            ldsm_x4(qah, qbh + t * 32);
            ldsm_x4(qal, qbl + t * 32);
#pragma unroll
            for (int g = 0; g < 4; ++g) {
                uint32_t kbh[4], kbl[4];
                const uint32_t ka = (g * 16 + krow) * AROWB + t * 32 + kof;
                ldsm_x4(kbh, sKh + ka);
                ldsm_x4(kbl, sKl + ka);
                mma16816(sfr[2*g],   qah, kbh);
                mma16816(sfr[2*g],   qal, kbh);
                mma16816(sfr[2*g],   qah, kbl);
                mma16816(sfr[2*g+1], qah, kbh + 2);
                mma16816(sfr[2*g+1], qal, kbh + 2);
                mma16816(sfr[2*g+1], qah, kbl + 2);
            }
        }

        const float cs = 0.1803368801111204f;
        const int rg0 = q0 + warp * 16 + (lane >> 2);
        if (kt >= 2 * qt) {
#pragma unroll
            for (int j = 0; j < 8; ++j) {
                const int cb = k0 + j * 8 + 2 * (lane & 3);
#pragma unroll
                for (int e = 0; e < 4; ++e) {
                    const int cg = cb + (e & 1);
                    const int rg = rg0 + ((e >> 1) << 3);
                    const float s = sfr[j][e] * cs;
                    sfr[j][e] = (cg > rg) ? -1e30f : s;
                }
            }
        } else {
#pragma unroll
            for (int j = 0; j < 8; ++j)
#pragma unroll
                for (int e = 0; e < 4; ++e) sfr[j][e] *= cs;
        }
        float mx0 = -1e30f, mx1 = -1e30f;
#pragma unroll
        for (int j = 0; j < 8; ++j) {
            mx0 = fmaxf(mx0, fmaxf(sfr[j][0], sfr[j][1]));
            mx1 = fmaxf(mx1, fmaxf(sfr[j][2], sfr[j][3]));
        }
        mx0 = fmaxf(mx0, __shfl_xor_sync(0xffffffffu, mx0, 1));
        mx0 = fmaxf(mx0, __shfl_xor_sync(0xffffffffu, mx0, 2));
        mx1 = fmaxf(mx1, __shfl_xor_sync(0xffffffffu, mx1, 1));
        mx1 = fmaxf(mx1, __shfl_xor_sync(0xffffffffu, mx1, 2));
        mx0 = fmaxf(mx0, m0);
        mx1 = fmaxf(mx1, m1);
        const float al0 = exp2f(m0 - mx0);
        const float al1 = exp2f(m1 - mx1);
        m0 = mx0; m1 = mx1;
        float s0 = 0.f, s1 = 0.f;
#pragma unroll
        for (int j = 0; j < 8; ++j) {
            float p0 = exp2f(sfr[j][0] - mx0);
            float p1 = exp2f(sfr[j][1] - mx0);
            float p2 = exp2f(sfr[j][2] - mx1);
            float p3 = exp2f(sfr[j][3] - mx1);
            sfr[j][0] = p0; sfr[j][1] = p1; sfr[j][2] = p2; sfr[j][3] = p3;
            s0 += p0 + p1; s1 += p2 + p3;
        }
        s0 += __shfl_xor_sync(0xffffffffu, s0, 1);
        s0 += __shfl_xor_sync(0xffffffffu, s0, 2);
        s1 += __shfl_xor_sync(0xffffffffu, s1, 1);
        s1 += __shfl_xor_sync(0xffffffffu, s1, 2);
        l0 = l0 * al0 + s0;
        l1 = l1 * al1 + s1;
#pragma unroll
        for (int j = 0; j < 8; ++j) {
            oac[j][0] *= al0; oac[j][1] *= al0;
            oac[j][2] *= al1; oac[j][3] *= al1;
        }

#pragma unroll
        for (int t = 0; t < 4; ++t) {
            const float* f0 = sfr[2*t];
            const float* f1 = sfr[2*t+1];
            uint32_t pah[4], pal[4];
            pah[0] = packbf(f0[0], f0[1]);
            pah[1] = packbf(f0[2], f0[3]);
            pah[2] = packbf(f1[0], f1[1]);
            pah[3] = packbf(f1[2], f1[3]);
            pal[0] = packbf(bfres(f0[0]), bfres(f0[1]));
            pal[1] = packbf(bfres(f0[2]), bfres(f0[3]));
            pal[2] = packbf(bfres(f1[0]), bfres(f1[1]));
            pal[3] = packbf(bfres(f1[2]), bfres(f1[3]));
#pragma unroll
            for (int np = 0; np < 4; ++np) {
                uint32_t vbh[4], vbl[4];
                const uint32_t va = (t * 16 + vrow) * AROWB + np * 32 + vof;
                ldsm_x4_t(vbh, sVh + va);
                ldsm_x4_t(vbl, sVl + va);
                mma16816(oac[2*np],   pah, vbh);
                mma16816(oac[2*np],   pal, vbh);
                mma16816(oac[2*np],   pah, vbl);
                mma16816(oac[2*np+1], pah, vbh + 2);
                mma16816(oac[2*np+1], pal, vbh + 2);
                mma16816(oac[2*np+1], pah, vbl + 2);
            }
        }
    }

    const float inv0 = 1.f / l0, inv1 = 1.f / l1;
    const int r0g = q0 + warp * 16 + (lane >> 2);
#pragma unroll
    for (int j = 0; j < 8; ++j) {
        const size_t off0 = base + (size_t)r0g * DD + j * 8 + 2 * (lane & 3);
        const size_t off1 = off0 + (size_t)8 * DD;
        const float v0 = oac[j][0] * inv0, v1 = oac[j][1] * inv0;
        const float v2 = oac[j][2] * inv1, v3 = oac[j][3] * inv1;
        __nv_bfloat16 h0 = __float2bfloat16(v0), h1 = __float2bfloat16(v1);
        __nv_bfloat16 h2 = __float2bfloat16(v2), h3 = __float2bfloat16(v3);
        *(__nv_bfloat162*)(ohi + off0) = __halves2bfloat162(h0, h1);
        *(__nv_bfloat162*)(ohi + off1) = __halves2bfloat162(h2, h3);
        *(__nv_bfloat162*)(olo + off0) = __halves2bfloat162(
            __float2bfloat16(v0 - __bfloat162float(h0)),
            __float2bfloat16(v1 - __bfloat162float(h1)));
        *(__nv_bfloat162*)(olo + off1) = __halves2bfloat162(
            __float2bfloat16(v2 - __bfloat162float(h2)),
            __float2bfloat16(v3 - __bfloat162float(h3)));
    }
}

// ---------------- host launcher -------------------------------------------------
extern "C" void kernel_launch(void* const* d_in, const int* in_sizes, int n_in,
                              void* d_out, int out_size) {
    const float* x     = (const float*)d_in[0];
    const float* ln1_g = (const float*)d_in[1];
    const float* ln1_b = (const float*)d_in[2];
    const float* wq    = (const float*)d_in[3];
    const float* bq    = (const float*)d_in[4];
    const float* wk    = (const float*)d_in[5];
    const float* bk    = (const float*)d_in[6];
    const float* wv    = (const float*)d_in[7];
    const float* bv    = (const float*)d_in[8];
    const float* wo    = (const float*)d_in[9];
    const float* bo    = (const float*)d_in[10];
    const float* ln2_g = (const float*)d_in[11];
    const float* ln2_b = (const float*)d_in[12];
    const float* w1    = (const float*)d_in[13];
    const float* b1    = (const float*)d_in[14];
    const float* w2    = (const float*)d_in[15];
    const float* b2    = (const float*)d_in[16];
    float* out = (float*)d_out;

    int8_t *h8h,*h8l,*o8h,*o8l,*h28h,*h28l,*a8h,*a8l;
    int8_t *wqkv8h,*wqkv8l,*wo8h,*wo8l,*w18h,*w18l,*w28h,*w28l;
    float *Sh,*So,*Sh2,*Sa2,*SBqkv,*SBo,*SB1,*SB2,*padd1;
    __nv_bfloat16 *qhi,*qlo,*khi,*klo,*vhi,*vlo,*ohi,*olo,*acthi,*actlo;
    cudaGetSymbolAddress((void**)&h8h, g_h8h);   cudaGetSymbolAddress((void**)&h8l, g_h8l);
    cudaGetSymbolAddress((void**)&o8h, g_o8h);   cudaGetSymbolAddress((void**)&o8l, g_o8l);
    cudaGetSymbolAddress((void**)&h28h,g_h28h);  cudaGetSymbolAddress((void**)&h28l,g_h28l);
    cudaGetSymbolAddress((void**)&a8h, g_a8h);   cudaGetSymbolAddress((void**)&a8l, g_a8l);
    cudaGetSymbolAddress((void**)&Sh,  g_Sh);    cudaGetSymbolAddress((void**)&So,  g_So);
    cudaGetSymbolAddress((void**)&Sh2, g_Sh2);   cudaGetSymbolAddress((void**)&Sa2, g_Sa2);
    cudaGetSymbolAddress((void**)&wqkv8h,g_wqkv8h); cudaGetSymbolAddress((void**)&wqkv8l,g_wqkv8l);
    cudaGetSymbolAddress((void**)&wo8h,g_wo8h);  cudaGetSymbolAddress((void**)&wo8l,g_wo8l);
    cudaGetSymbolAddress((void**)&w18h,g_w18h);  cudaGetSymbolAddress((void**)&w18l,g_w18l);
    cudaGetSymbolAddress((void**)&w28h,g_w28h);  cudaGetSymbolAddress((void**)&w28l,g_w28l);
    cudaGetSymbolAddress((void**)&SBqkv,g_SBqkv);cudaGetSymbolAddress((void**)&SBo,g_SBo);
    cudaGetSymbolAddress((void**)&SB1, g_SB1);   cudaGetSymbolAddress((void**)&SB2, g_SB2);
    cudaGetSymbolAddress((void**)&padd1,g_add1);
    cudaGetSymbolAddress((void**)&qhi, g_q_hi);  cudaGetSymbolAddress((void**)&qlo, g_q_lo);
    cudaGetSymbolAddress((void**)&khi, g_k_hi);  cudaGetSymbolAddress((void**)&klo, g_k_lo);
    cudaGetSymbolAddress((void**)&vhi, g_v_hi);  cudaGetSymbolAddress((void**)&vlo, g_v_lo);
    cudaGetSymbolAddress((void**)&ohi, g_o_hi);  cudaGetSymbolAddress((void**)&olo, g_o_lo);
    cudaGetSymbolAddress((void**)&acthi,g_act_hi);cudaGetSymbolAddress((void**)&actlo,g_act_lo);

    cudaFuncSetAttribute(i8_gemm<1,false,false,true >, cudaFuncAttributeMaxDynamicSharedMemorySize, IGEMM_SMEM);
    cudaFuncSetAttribute(i8_gemm<0,true, false,false>, cudaFuncAttributeMaxDynamicSharedMemorySize, IGEMM_SMEM);
    cudaFuncSetAttribute(i8_gemm<1,false,true ,false>, cudaFuncAttributeMaxDynamicSharedMemorySize, IGEMM_SMEM);
    cudaFuncSetAttribute(attn_mma, cudaFuncAttributeMaxDynamicSharedMemorySize, ATT_SMEM);

    // weight quantization (int8 hi/lo, [N,K], per-col scales)
    wquant_kernel<<<DD/32, 256>>>(wq, wqkv8h,                 wqkv8l,                 SBqkv,        DD, DD);
    wquant_kernel<<<DD/32, 256>>>(wk, wqkv8h + (size_t)DD*DD, wqkv8l + (size_t)DD*DD, SBqkv + DD,   DD, DD);
    wquant_kernel<<<DD/32, 256>>>(wv, wqkv8h + (size_t)2*DD*DD, wqkv8l + (size_t)2*DD*DD, SBqkv + 2*DD, DD, DD);
    wquant_kernel<<<DD/32, 256>>>(wo, wo8h, wo8l, SBo, DD, DD);
    wquant_kernel<<<FF/32, 256>>>(w1, w18h, w18l, SB1, DD, FF);
    wquant_kernel<<<DD/32, 256>>>(w2, w28h, w28l, SB2, FF, DD);

    // ln1 -> int8 quant
    ln_quant_kernel<<<NTOK, 256>>>(x, ln1_g, ln1_b, h8h, h8l, Sh);

    // fused QKV int8 GEMM -> q/k/v bf16 pairs
    {
        dim3 grid(3*DD/128, NTOK/128);
        i8_gemm<1,false,false,true><<<grid, 256, IGEMM_SMEM>>>(
            h8h, h8l, wqkv8h, wqkv8l, Sh, SBqkv, bq, bk, bv, nullptr,
            nullptr, qhi, qlo, khi, klo, vhi, vlo, NTOK, 3*DD, DD);
    }

    // attention (bf16x3 tensor-core flash)
    {
        dim3 grid(SS/128, BB*HH);
        attn_mma<<<grid, 256, ATT_SMEM>>>(qhi, qlo, khi, klo, vhi, vlo, ohi, olo);
    }

    // quantize attention output
    aquant_kernel<<<NTOK, 256>>>(ohi, olo, o8h, o8l, So, DD);

    // O-proj + residual: add1 = x + o@wo + bo
    {
        dim3 grid(DD/128, NTOK/128);
        i8_gemm<0,true,false,false><<<grid, 256, IGEMM_SMEM>>>(
            o8h, o8l, wo8h, wo8l, So, SBo, bo, nullptr, nullptr, x,
            padd1, nullptr, nullptr, nullptr, nullptr, nullptr, nullptr, NTOK, DD, DD);
    }

    // ln2 -> int8 quant
    ln_quant_kernel<<<NTOK, 256>>>(padd1, ln2_g, ln2_b, h28h, h28l, Sh2);

    // MLP up + gelu -> bf16 pair
    {
        dim3 grid(FF/128, NTOK/128);
        i8_gemm<1,false,true,false><<<grid, 256, IGEMM_SMEM>>>(
            h28h, h28l, w18h, w18l, Sh2, SB1, b1, nullptr, nullptr, nullptr,
            nullptr, acthi, actlo, nullptr, nullptr, nullptr, nullptr, NTOK, FF, DD);
    }

    // quantize activations
    aquant_kernel<<<NTOK, 256>>>(acthi, actlo, a8h, a8l, Sa2, FF);

    // MLP down + residual -> out
    {
        dim3 grid(DD/128, NTOK/128);
        i8_gemm<0,true,false,false><<<grid, 256, IGEMM_SMEM>>>(
            a8h, a8l, w28h, w28l, Sa2, SB2, b2, nullptr, nullptr, padd1,
            out, nullptr, nullptr, nullptr, nullptr, nullptr, nullptr, NTOK, DD, FF);
    }
}

// round 7
// speedup vs baseline: 3.5631x; 3.5631x over previous
#include <cuda_runtime.h>
#include <cuda_fp16.h>
#include <math.h>
#include <stdint.h>

// Problem dims (fixed)
#define BB 2
#define SS 2048
#define DD 1024
#define HH 16
#define DHH 64
#define FF 4096
#define NTOK (BB*SS)   // 4096

// ---------------- scratch (device globals) -----------------------------------
__device__ __half g_h_hi [NTOK*DD], g_h_lo [NTOK*DD];
__device__ __half g_q [NTOK*DD];
__device__ __half g_k [NTOK*DD];
__device__ __half g_v [NTOK*DD];
__device__ __half g_o_hi [NTOK*DD], g_o_lo [NTOK*DD];
__device__ float  g_add1[NTOK*DD];
__device__ __half g_h2_hi[NTOK*DD], g_h2_lo[NTOK*DD];
__device__ __half g_act_hi[NTOK*FF], g_act_lo[NTOK*FF];
__device__ __half g_wq[DD*DD], g_wk[DD*DD], g_wv[DD*DD], g_wo[DD*DD];
__device__ __half g_w1[DD*FF], g_w2[FF*DD];

// ---------------- helpers ------------------------------------------------------
__device__ __forceinline__ uint32_t smem_u32(const void* p) {
    uint32_t a;
    asm("{ .reg .u64 t; cvta.to.shared.u64 t, %1; cvt.u32.u64 %0, t; }" : "=r"(a) : "l"(p));
    return a;
}
__device__ __forceinline__ void cp_async16(uint32_t dst, const void* src) {
    asm volatile("cp.async.cg.shared.global [%0], [%1], 16;"
                 :: "r"(dst), "l"(src) : "memory");
}
__device__ __forceinline__ void cp_commit() {
    asm volatile("cp.async.commit_group;" ::: "memory");
}
template<int N>
__device__ __forceinline__ void cp_wait() {
    asm volatile("cp.async.wait_group %0;" :: "n"(N) : "memory");
}
__device__ __forceinline__ void ldsm_x4(uint32_t* r, uint32_t addr) {
    asm volatile("ldmatrix.sync.aligned.m8n8.x4.shared.b16 {%0,%1,%2,%3}, [%4];"
                 : "=r"(r[0]), "=r"(r[1]), "=r"(r[2]), "=r"(r[3]) : "r"(addr));
}
__device__ __forceinline__ void ldsm_x4_t(uint32_t* r, uint32_t addr) {
    asm volatile("ldmatrix.sync.aligned.m8n8.x4.trans.shared.b16 {%0,%1,%2,%3}, [%4];"
                 : "=r"(r[0]), "=r"(r[1]), "=r"(r[2]), "=r"(r[3]) : "r"(addr));
}
// fp16 MMA, fp32 accumulate
__device__ __forceinline__ void mma16816h(float* d, const uint32_t* a, const uint32_t* b) {
    asm volatile(
        "mma.sync.aligned.m16n8k16.row.col.f32.f16.f16.f32 "
        "{%0,%1,%2,%3}, {%4,%5,%6,%7}, {%8,%9}, {%0,%1,%2,%3};"
        : "+f"(d[0]), "+f"(d[1]), "+f"(d[2]), "+f"(d[3])
        : "r"(a[0]), "r"(a[1]), "r"(a[2]), "r"(a[3]), "r"(b[0]), "r"(b[1]));
}
__device__ __forceinline__ uint32_t packh(float a, float b) {
    __half2 t = __floats2half2_rn(a, b);
    return *reinterpret_cast<uint32_t*>(&t);
}

// ---------------- LayerNorm -> fp16 hi/lo split --------------------------------
__global__ void ln_split_kernel(const float* __restrict__ x,
                                const float* __restrict__ g,
                                const float* __restrict__ b,
                                __half* __restrict__ yhi,
                                __half* __restrict__ ylo) {
    const int row = blockIdx.x;
    const int tid = threadIdx.x;   // 256
    const float* xr = x + (size_t)row * DD;

    float v[4];
    float s = 0.f, s2 = 0.f;
#pragma unroll
    for (int i = 0; i < 4; ++i) {
        v[i] = xr[tid + i * 256];
        s += v[i]; s2 += v[i] * v[i];
    }
    for (int off = 16; off > 0; off >>= 1) {
        s  += __shfl_down_sync(0xffffffffu, s,  off);
        s2 += __shfl_down_sync(0xffffffffu, s2, off);
    }
    __shared__ float rs[8], rs2[8];
    if ((tid & 31) == 0) { rs[tid >> 5] = s; rs2[tid >> 5] = s2; }
    __syncthreads();
    if (tid < 8) { s = rs[tid]; s2 = rs2[tid]; } else { s = 0.f; s2 = 0.f; }
    if (tid < 32) {
        for (int off = 4; off > 0; off >>= 1) {
            s  += __shfl_down_sync(0xffffffffu, s,  off);
            s2 += __shfl_down_sync(0xffffffffu, s2, off);
        }
        if (tid == 0) { rs[0] = s; rs2[0] = s2; }
    }
    __syncthreads();
    const float mean = rs[0] * (1.0f / DD);
    const float var  = rs2[0] * (1.0f / DD) - mean * mean;
    const float inv  = rsqrtf(var + 1e-5f);
    __half* yh = yhi + (size_t)row * DD;
    __half* yl = ylo + (size_t)row * DD;
#pragma unroll
    for (int i = 0; i < 4; ++i) {
        const int c = tid + i * 256;
        float o = (v[i] - mean) * inv * g[c] + b[c];
        __half h = __float2half_rn(o);
        yh[c] = h;
        yl[c] = __float2half_rn(o - __half2float(h));
    }
}

// ---------------- weight transpose: w[K,N] fp32 -> [N,K] fp16 (single) ---------
__global__ void wsplit_kernel(const float* __restrict__ w,
                              __half* __restrict__ bh, int K, int N) {
    __shared__ float t[32][33];
    const int bx = blockIdx.x;   // n tile
    const int by = blockIdx.y;   // k tile
    const int tx = threadIdx.x & 31;
    const int ty = threadIdx.x >> 5;   // 0..7
#pragma unroll
    for (int i = 0; i < 32; i += 8)
        t[ty + i][tx] = w[(size_t)(by * 32 + ty + i) * N + bx * 32 + tx];
    __syncthreads();
#pragma unroll
    for (int i = 0; i < 32; i += 8) {
        const int n = bx * 32 + ty + i;
        const int k = by * 32 + tx;
        bh[(size_t)n * K + k] = __float2half_rn(t[tx][ty + i]);
    }
}

// ---------------- fp16x2 GEMM: C[M,N] = A[M,K] @ B^T ([N,K] fp16) --------------
// C = Ahi*B + Alo*B, fp32 accumulate (A corrected to 2^-21, B fp16 single).
// CTA tile 128x128, BK=32, 8 warps (4x2), warp tile 32x64, double buffer.
#define ROWB 80
#define TILESZ (128*ROWB)      // 10240
#define BUF3   (3*TILESZ)      // Ahi, Alo, B = 30720
#define GEMM_SMEM (2*BUF3 + 512)

__device__ __forceinline__ void issue_chunk3(const __half* const* tp, int k0,
                                             uint32_t buf, int tid, int K) {
#pragma unroll
    for (int t = 0; t < 3; ++t) {
#pragma unroll
        for (int u = 0; u < 2; ++u) {
            const int lin = tid + u * 256;       // 0..511
            const int r = lin >> 2;              // 0..127
            const int c4 = lin & 3;              // 16B chunk
            const void* src = tp[t] + (size_t)r * K + k0 + c4 * 8;
            cp_async16(buf + t * TILESZ + r * ROWB + c4 * 16, src);
        }
    }
    cp_commit();
}

template<int OUTMODE /*0=f32, 1=fp16 pair, 2=fp16 single*/, bool HAS_RES, bool DO_GELU>
__global__ void __launch_bounds__(256)
tc_gemm(const __half* __restrict__ Ahi, const __half* __restrict__ Alo,
        const __half* __restrict__ B,
        const float* __restrict__ bias, const float* __restrict__ res,
        float* __restrict__ Cf,
        __half* __restrict__ Chi, __half* __restrict__ Clo,
        int M, int N, int K) {
    extern __shared__ char smem[];
    const uint32_t sbase = smem_u32(smem);
    float* bias_s = (float*)(smem + 2 * BUF3);

    const int tid  = threadIdx.x;
    const int wid  = tid >> 5;
    const int lane = tid & 31;
    const int wm = wid >> 1;
    const int wn = wid & 1;
    const int bx = blockIdx.x, by = blockIdx.y;

    if (tid < 128) bias_s[tid] = bias[bx * 128 + tid];

    const size_t aoff = (size_t)by * 128 * K;
    const size_t boff = (size_t)bx * 128 * K;
    const __half* tp[3] = { Ahi + aoff, Alo + aoff, B + boff };

    const int nchunk = K >> 5;

    float acc[2][8][4];
#pragma unroll
    for (int mt = 0; mt < 2; ++mt)
#pragma unroll
        for (int nt = 0; nt < 8; ++nt)
#pragma unroll
            for (int e = 0; e < 4; ++e) acc[mt][nt][e] = 0.f;

    const int a_row = wm * 32 + (lane & 15);
    const int a_kof = (lane >> 4) << 3;
    const int b_row = wn * 64 + (lane & 7) + ((lane >> 4) << 3);
    const int b_kof = ((lane >> 3) & 1) << 3;

    issue_chunk3(tp, 0, sbase, tid, K);

    for (int i = 0; i < nchunk; ++i) {
        if (i + 1 < nchunk)
            issue_chunk3(tp, (i + 1) << 5, sbase + ((i + 1) & 1) * BUF3, tid, K);
        if (i + 1 < nchunk) cp_wait<1>(); else cp_wait<0>();
        __syncthreads();

        const uint32_t buf = sbase + (i & 1) * BUF3;
        const uint32_t aAh = buf + a_row * ROWB;
        const uint32_t aAl = aAh + TILESZ;
        const uint32_t aB  = buf + 2 * TILESZ + b_row * ROWB;

#pragma unroll
        for (int ks = 0; ks < 2; ++ks) {
            const int ak = (ks * 16 + a_kof) * 2;
            const int bk = (ks * 16 + b_kof) * 2;
            uint32_t ah[2][4], al[2][4], bh[8][2];
#pragma unroll
            for (int mt = 0; mt < 2; ++mt) {
                ldsm_x4(ah[mt], aAh + mt * 16 * ROWB + ak);
                ldsm_x4(al[mt], aAl + mt * 16 * ROWB + ak);
            }
#pragma unroll
            for (int p = 0; p < 4; ++p) {
                uint32_t r[4];
                ldsm_x4(r, aB + p * 16 * ROWB + bk);
                bh[2*p][0] = r[0]; bh[2*p][1] = r[1];
                bh[2*p+1][0] = r[2]; bh[2*p+1][1] = r[3];
            }
#pragma unroll
            for (int mt = 0; mt < 2; ++mt)
#pragma unroll
                for (int nt = 0; nt < 8; ++nt) {
                    mma16816h(acc[mt][nt], ah[mt], bh[nt]);
                    mma16816h(acc[mt][nt], al[mt], bh[nt]);
                }
        }
        __syncthreads();
    }

    const int mbase = by * 128 + wm * 32;
    const int nloc0 = wn * 64;
#pragma unroll
    for (int mt = 0; mt < 2; ++mt) {
#pragma unroll
        for (int half = 0; half < 2; ++half) {
            const int m = mbase + mt * 16 + (lane >> 2) + half * 8;
#pragma unroll
            for (int nt = 0; nt < 8; ++nt) {
                const int nloc = nloc0 + nt * 8 + 2 * (lane & 3);
                const int n = bx * 128 + nloc;
                float v0 = acc[mt][nt][half * 2 + 0] + bias_s[nloc];
                float v1 = acc[mt][nt][half * 2 + 1] + bias_s[nloc + 1];
                if (DO_GELU) {
                    v0 = 0.5f * v0 * (1.0f + erff(v0 * 0.70710678118654752f));
                    v1 = 0.5f * v1 * (1.0f + erff(v1 * 0.70710678118654752f));
                }
                if (HAS_RES) {
                    const float2 rv = *(const float2*)(res + (size_t)m * N + n);
                    v0 += rv.x; v1 += rv.y;
                }
                if (OUTMODE == 0) {
                    *(float2*)(Cf + (size_t)m * N + n) = make_float2(v0, v1);
                } else if (OUTMODE == 2) {
                    *(__half2*)(Chi + (size_t)m * N + n) = __floats2half2_rn(v0, v1);
                } else {
                    __half h0 = __float2half_rn(v0);
                    __half h1 = __float2half_rn(v1);
                    __half l0 = __float2half_rn(v0 - __half2float(h0));
                    __half l1 = __float2half_rn(v1 - __half2float(h1));
                    *(__half2*)(Chi + (size_t)m * N + n) = __halves2half2(h0, h1);
                    *(__half2*)(Clo + (size_t)m * N + n) = __halves2half2(l0, l1);
                }
            }
        }
    }
}

// ---------------- Flash attention via mma.sync (fp16 single-term, causal) ------
// CTA: 128 q-rows x DH=64, 8 warps. K-tiles of 64 keys. O written as fp16 pair.
#define AROWB 144
#define ATT_SMEM (AROWB*(128 + 64 + 64))   // Q + K + V = 36864

__global__ void __launch_bounds__(256, 2)
attn_mma(const __half* __restrict__ q, const __half* __restrict__ k,
         const __half* __restrict__ v,
         __half* __restrict__ ohi, __half* __restrict__ olo) {
    extern __shared__ char sm[];
    const uint32_t sb = smem_u32(sm);
    const uint32_t sQ = sb;
    const uint32_t sK = sb + 128 * AROWB;
    const uint32_t sV = sK + 64 * AROWB;

    const int qt = gridDim.x - 1 - blockIdx.x;   // big tiles first
    const int bh = blockIdx.y;
    const int b = bh >> 4, h = bh & 15;
    const size_t base = (size_t)b * SS * DD + (size_t)h * DHH;
    const int q0 = qt * 128;

    const int tid = threadIdx.x, warp = tid >> 5, lane = tid & 31;

    // stage Q
#pragma unroll
    for (int u = 0; u < 4; ++u) {
        const int lin = tid + u * 256;       // 0..1023
        const int r = lin >> 3, c = lin & 7;
        cp_async16(sQ + r * AROWB + c * 16, q + base + (size_t)(q0 + r) * DD + c * 8);
    }
    cp_commit();

    float sfr[8][4], oac[8][4];
    float m0 = -1e30f, m1 = -1e30f, l0 = 0.f, l1 = 0.f;
#pragma unroll
    for (int j = 0; j < 8; ++j)
#pragma unroll
        for (int e = 0; e < 4; ++e) oac[j][e] = 0.f;

    const uint32_t qb = sQ + (warp * 16 + (lane & 15)) * AROWB + (((lane >> 4) << 3) << 1);
    const int krow = (lane & 7) + ((lane >> 4) << 3);
    const uint32_t kof = (((lane >> 3) & 1) << 3) << 1;
    const int vrow = lane & 15;
    const uint32_t vof = (((lane >> 4) << 3)) << 1;

    cp_wait<0>();
    __syncthreads();

    const int ntile = qt * 2 + 2;
    for (int kt = 0; kt < ntile; ++kt) {
        const int k0 = kt * 64;
        __syncthreads();
        {
            const __half* srck = k + base + (size_t)k0 * DD;
            const __half* srcv = v + base + (size_t)k0 * DD;
#pragma unroll
            for (int u = 0; u < 2; ++u) {
                const int lin = tid + u * 256;   // 0..511 -> 64 rows x 8 chunks
                const int rr = lin >> 3, cc = lin & 7;
                const size_t go = (size_t)rr * DD + cc * 8;
                const uint32_t so = rr * AROWB + cc * 16;
                cp_async16(sK + so, srck + go);
                cp_async16(sV + so, srcv + go);
            }
            cp_commit(); cp_wait<0>();
            __syncthreads();
        }

        // ---- scores S = Q @ K^T (single fp16 term) ----
#pragma unroll
        for (int j = 0; j < 8; ++j)
#pragma unroll
            for (int e = 0; e < 4; ++e) sfr[j][e] = 0.f;
#pragma unroll
        for (int t = 0; t < 4; ++t) {
            uint32_t qa[4];
            ldsm_x4(qa, qb + t * 32);
#pragma unroll
            for (int g = 0; g < 4; ++g) {
                uint32_t kb[4];
                ldsm_x4(kb, sK + (g * 16 + krow) * AROWB + t * 32 + kof);
                mma16816h(sfr[2*g],   qa, kb);
                mma16816h(sfr[2*g+1], qa, kb + 2);
            }
        }

        // ---- online softmax (base-2 domain, warp-local rows) ----
        const float cs = 0.1803368801111204f;   // 0.125 * log2(e)
        const int rg0 = q0 + warp * 16 + (lane >> 2);
        if (kt >= 2 * qt) {
#pragma unroll
            for (int j = 0; j < 8; ++j) {
                const int cb = k0 + j * 8 + 2 * (lane & 3);
#pragma unroll
                for (int e = 0; e < 4; ++e) {
                    const int cg = cb + (e & 1);
                    const int rg = rg0 + ((e >> 1) << 3);
                    const float s = sfr[j][e] * cs;
                    sfr[j][e] = (cg > rg) ? -1e30f : s;
                }
            }
        } else {
#pragma unroll
            for (int j = 0; j < 8; ++j)
#pragma unroll
                for (int e = 0; e < 4; ++e) sfr[j][e] *= cs;
        }
        float mx0 = -1e30f, mx1 = -1e30f;
#pragma unroll
        for (int j = 0; j < 8; ++j) {
            mx0 = fmaxf(mx0, fmaxf(sfr[j][0], sfr[j][1]));
            mx1 = fmaxf(mx1, fmaxf(sfr[j][2], sfr[j][3]));
        }
        mx0 = fmaxf(mx0, __shfl_xor_sync(0xffffffffu, mx0, 1));
        mx0 = fmaxf(mx0, __shfl_xor_sync(0xffffffffu, mx0, 2));
        mx1 = fmaxf(mx1, __shfl_xor_sync(0xffffffffu, mx1, 1));
        mx1 = fmaxf(mx1, __shfl_xor_sync(0xffffffffu, mx1, 2));
        mx0 = fmaxf(mx0, m0);
        mx1 = fmaxf(mx1, m1);
        const float al0 = exp2f(m0 - mx0);
        const float al1 = exp2f(m1 - mx1);
        m0 = mx0; m1 = mx1;
        float s0 = 0.f, s1 = 0.f;
#pragma unroll
        for (int j = 0; j < 8; ++j) {
            float p0 = exp2f(sfr[j][0] - mx0);
            float p1 = exp2f(sfr[j][1] - mx0);
            float p2 = exp2f(sfr[j][2] - mx1);
            float p3 = exp2f(sfr[j][3] - mx1);
            sfr[j][0] = p0; sfr[j][1] = p1; sfr[j][2] = p2; sfr[j][3] = p3;
            s0 += p0 + p1; s1 += p2 + p3;
        }
        s0 += __shfl_xor_sync(0xffffffffu, s0, 1);
        s0 += __shfl_xor_sync(0xffffffffu, s0, 2);
        s1 += __shfl_xor_sync(0xffffffffu, s1, 1);
        s1 += __shfl_xor_sync(0xffffffffu, s1, 2);
        l0 = l0 * al0 + s0;
        l1 = l1 * al1 + s1;
#pragma unroll
        for (int j = 0; j < 8; ++j) {
            oac[j][0] *= al0; oac[j][1] *= al0;
            oac[j][2] *= al1; oac[j][3] *= al1;
        }

        // ---- O += P @ V (single fp16 term) ----
#pragma unroll
        for (int t = 0; t < 4; ++t) {
            const float* f0 = sfr[2*t];
            const float* f1 = sfr[2*t+1];
            uint32_t pa[4];
            pa[0] = packh(f0[0], f0[1]);
            pa[1] = packh(f0[2], f0[3]);
            pa[2] = packh(f1[0], f1[1]);
            pa[3] = packh(f1[2], f1[3]);
#pragma unroll
            for (int np = 0; np < 4; ++np) {
                uint32_t vb[4];
                ldsm_x4_t(vb, sV + (t * 16 + vrow) * AROWB + np * 32 + vof);
                mma16816h(oac[2*np],   pa, vb);
                mma16816h(oac[2*np+1], pa, vb + 2);
            }
        }
    }

    // ---- write O as fp16 pair ----
    const float inv0 = 1.f / l0, inv1 = 1.f / l1;
    const int r0g = q0 + warp * 16 + (lane >> 2);
#pragma unroll
    for (int j = 0; j < 8; ++j) {
        const size_t off0 = base + (size_t)r0g * DD + j * 8 + 2 * (lane & 3);
        const size_t off1 = off0 + (size_t)8 * DD;
        const float v0 = oac[j][0] * inv0, v1 = oac[j][1] * inv0;
        const float v2 = oac[j][2] * inv1, v3 = oac[j][3] * inv1;
        __half h0 = __float2half_rn(v0), h1 = __float2half_rn(v1);
        __half h2 = __float2half_rn(v2), h3 = __float2half_rn(v3);
        *(__half2*)(ohi + off0) = __halves2half2(h0, h1);
        *(__half2*)(ohi + off1) = __halves2half2(h2, h3);
        *(__half2*)(olo + off0) = __halves2half2(
            __float2half_rn(v0 - __half2float(h0)),
            __float2half_rn(v1 - __half2float(h1)));
        *(__half2*)(olo + off1) = __halves2half2(
            __float2half_rn(v2 - __half2float(h2)),
            __float2half_rn(v3 - __half2float(h3)));
    }
}

// ---------------- host launcher -------------------------------------------------
extern "C" void kernel_launch(void* const* d_in, const int* in_sizes, int n_in,
                              void* d_out, int out_size) {
    const float* x     = (const float*)d_in[0];
    const float* ln1_g = (const float*)d_in[1];
    const float* ln1_b = (const float*)d_in[2];
    const float* wq    = (const float*)d_in[3];
    const float* bq    = (const float*)d_in[4];
    const float* wk    = (const float*)d_in[5];
    const float* bk    = (const float*)d_in[6];
    const float* wv    = (const float*)d_in[7];
    const float* bv    = (const float*)d_in[8];
    const float* wo    = (const float*)d_in[9];
    const float* bo    = (const float*)d_in[10];
    const float* ln2_g = (const float*)d_in[11];
    const float* ln2_b = (const float*)d_in[12];
    const float* w1    = (const float*)d_in[13];
    const float* b1    = (const float*)d_in[14];
    const float* w2    = (const float*)d_in[15];
    const float* b2    = (const float*)d_in[16];
    float* out = (float*)d_out;

    __half *hhi, *hlo, *pq, *pk, *pv, *ohi, *olo, *h2hi, *h2lo, *acthi, *actlo;
    __half *pwq, *pwk, *pwv, *pwo, *pw1, *pw2;
    float *padd1;
    cudaGetSymbolAddress((void**)&hhi,  g_h_hi);  cudaGetSymbolAddress((void**)&hlo,  g_h_lo);
    cudaGetSymbolAddress((void**)&pq,   g_q);
    cudaGetSymbolAddress((void**)&pk,   g_k);
    cudaGetSymbolAddress((void**)&pv,   g_v);
    cudaGetSymbolAddress((void**)&ohi,  g_o_hi);  cudaGetSymbolAddress((void**)&olo,  g_o_lo);
    cudaGetSymbolAddress((void**)&padd1,g_add1);
    cudaGetSymbolAddress((void**)&h2hi, g_h2_hi); cudaGetSymbolAddress((void**)&h2lo, g_h2_lo);
    cudaGetSymbolAddress((void**)&acthi,g_act_hi);cudaGetSymbolAddress((void**)&actlo,g_act_lo);
    cudaGetSymbolAddress((void**)&pwq,  g_wq);    cudaGetSymbolAddress((void**)&pwk,  g_wk);
    cudaGetSymbolAddress((void**)&pwv,  g_wv);    cudaGetSymbolAddress((void**)&pwo,  g_wo);
    cudaGetSymbolAddress((void**)&pw1,  g_w1);    cudaGetSymbolAddress((void**)&pw2,  g_w2);

    cudaFuncSetAttribute(tc_gemm<2,false,false>, cudaFuncAttributeMaxDynamicSharedMemorySize, GEMM_SMEM);
    cudaFuncSetAttribute(tc_gemm<0,true, false>, cudaFuncAttributeMaxDynamicSharedMemorySize, GEMM_SMEM);
    cudaFuncSetAttribute(tc_gemm<1,false,true >, cudaFuncAttributeMaxDynamicSharedMemorySize, GEMM_SMEM);
    cudaFuncSetAttribute(attn_mma, cudaFuncAttributeMaxDynamicSharedMemorySize, ATT_SMEM);

    dim3 gridD(DD/128, NTOK/128);
    dim3 gridF(FF/128, NTOK/128);

    // #1 ln1 -> fp16 pair
    ln_split_kernel<<<NTOK, 256>>>(x, ln1_g, ln1_b, hhi, hlo);
    // #2, #3 weight transposes for Q, K
    wsplit_kernel<<<dim3(DD/32, DD/32), 256>>>(wq, pwq, DD, DD);
    wsplit_kernel<<<dim3(DD/32, DD/32), 256>>>(wk, pwk, DD, DD);
    // #4 (ncu-profiled slot): Q projection GEMM -> fp16 single
    tc_gemm<2,false,false><<<gridD, 256, GEMM_SMEM>>>(hhi, hlo, pwq, bq, nullptr, nullptr, pq, nullptr, NTOK, DD, DD);
    // #5 wv split, #6 K GEMM, #7 V GEMM
    wsplit_kernel<<<dim3(DD/32, DD/32), 256>>>(wv, pwv, DD, DD);
    tc_gemm<2,false,false><<<gridD, 256, GEMM_SMEM>>>(hhi, hlo, pwk, bk, nullptr, nullptr, pk, nullptr, NTOK, DD, DD);
    tc_gemm<2,false,false><<<gridD, 256, GEMM_SMEM>>>(hhi, hlo, pwv, bv, nullptr, nullptr, pv, nullptr, NTOK, DD, DD);

    // #8 attention (single-term fp16 flash) -> o fp16 pair
    {
        dim3 grid(SS/128, BB*HH);
        attn_mma<<<grid, 256, ATT_SMEM>>>(pq, pk, pv, ohi, olo);
    }

    // #9 wo split, #10 O-proj + residual: add1 = x + o@wo + bo
    wsplit_kernel<<<dim3(DD/32, DD/32), 256>>>(wo, pwo, DD, DD);
    tc_gemm<0,true,false><<<gridD, 256, GEMM_SMEM>>>(ohi, olo, pwo, bo, x, padd1, nullptr, nullptr, NTOK, DD, DD);

    // #11 ln2, #12 w1 split
    ln_split_kernel<<<NTOK, 256>>>(padd1, ln2_g, ln2_b, h2hi, h2lo);
    wsplit_kernel<<<dim3(FF/32, DD/32), 256>>>(w1, pw1, DD, FF);

    // #13 MLP up + gelu -> fp16 pair
    tc_gemm<1,false,true><<<gridF, 256, GEMM_SMEM>>>(h2hi, h2lo, pw1, b1, nullptr, nullptr, acthi, actlo, NTOK, FF, DD);

    // #14 w2 split, #15 MLP down + residual -> out
    wsplit_kernel<<<dim3(DD/32, FF/32), 256>>>(w2, pw2, FF, DD);
    tc_gemm<0,true,false><<<gridD, 256, GEMM_SMEM>>>(acthi, actlo, pw2, b2, padd1, out, nullptr, nullptr, NTOK, DD, FF);
}

// round 8
// speedup vs baseline: 5.3785x; 1.5095x over previous
#include <cuda_runtime.h>
#include <cuda_fp16.h>
#include <math.h>
#include <stdint.h>

// Problem dims (fixed)
#define BB 2
#define SS 2048
#define DD 1024
#define HH 16
#define DHH 64
#define FF 4096
#define NTOK (BB*SS)   // 4096

// ---------------- scratch (device globals) -----------------------------------
__device__ __half g_h  [NTOK*DD];
__device__ __half g_q  [NTOK*DD];
__device__ __half g_k  [NTOK*DD];
__device__ __half g_v  [NTOK*DD];
__device__ __half g_o  [NTOK*DD];
__device__ float  g_add1[NTOK*DD];
__device__ __half g_h2 [NTOK*DD];
__device__ __half g_act[NTOK*FF];
__device__ __half g_wq[DD*DD], g_wk[DD*DD], g_wv[DD*DD], g_wo[DD*DD];
__device__ __half g_w1[DD*FF], g_w2[FF*DD];

// ---------------- helpers ------------------------------------------------------
__device__ __forceinline__ uint32_t smem_u32(const void* p) {
    uint32_t a;
    asm("{ .reg .u64 t; cvta.to.shared.u64 t, %1; cvt.u32.u64 %0, t; }" : "=r"(a) : "l"(p));
    return a;
}
__device__ __forceinline__ void cp_async16(uint32_t dst, const void* src) {
    asm volatile("cp.async.cg.shared.global [%0], [%1], 16;"
                 :: "r"(dst), "l"(src) : "memory");
}
__device__ __forceinline__ void cp_commit() {
    asm volatile("cp.async.commit_group;" ::: "memory");
}
template<int N>
__device__ __forceinline__ void cp_wait() {
    asm volatile("cp.async.wait_group %0;" :: "n"(N) : "memory");
}
__device__ __forceinline__ void ldsm_x4(uint32_t* r, uint32_t addr) {
    asm volatile("ldmatrix.sync.aligned.m8n8.x4.shared.b16 {%0,%1,%2,%3}, [%4];"
                 : "=r"(r[0]), "=r"(r[1]), "=r"(r[2]), "=r"(r[3]) : "r"(addr));
}
__device__ __forceinline__ void ldsm_x4_t(uint32_t* r, uint32_t addr) {
    asm volatile("ldmatrix.sync.aligned.m8n8.x4.trans.shared.b16 {%0,%1,%2,%3}, [%4];"
                 : "=r"(r[0]), "=r"(r[1]), "=r"(r[2]), "=r"(r[3]) : "r"(addr));
}
__device__ __forceinline__ void mma16816h(float* d, const uint32_t* a, const uint32_t* b) {
    asm volatile(
        "mma.sync.aligned.m16n8k16.row.col.f32.f16.f16.f32 "
        "{%0,%1,%2,%3}, {%4,%5,%6,%7}, {%8,%9}, {%0,%1,%2,%3};"
        : "+f"(d[0]), "+f"(d[1]), "+f"(d[2]), "+f"(d[3])
        : "r"(a[0]), "r"(a[1]), "r"(a[2]), "r"(a[3]), "r"(b[0]), "r"(b[1]));
}
__device__ __forceinline__ uint32_t packh(float a, float b) {
    __half2 t = __floats2half2_rn(a, b);
    return *reinterpret_cast<uint32_t*>(&t);
}

// ---------------- LayerNorm -> fp16 ---------------------------------------------
__global__ void ln_half_kernel(const float* __restrict__ x,
                               const float* __restrict__ g,
                               const float* __restrict__ b,
                               __half* __restrict__ y) {
    const int row = blockIdx.x;
    const int tid = threadIdx.x;   // 256
    const float* xr = x + (size_t)row * DD;

    float v[4];
    float s = 0.f, s2 = 0.f;
#pragma unroll
    for (int i = 0; i < 4; ++i) {
        v[i] = xr[tid + i * 256];
        s += v[i]; s2 += v[i] * v[i];
    }
    for (int off = 16; off > 0; off >>= 1) {
        s  += __shfl_down_sync(0xffffffffu, s,  off);
        s2 += __shfl_down_sync(0xffffffffu, s2, off);
    }
    __shared__ float rs[8], rs2[8];
    if ((tid & 31) == 0) { rs[tid >> 5] = s; rs2[tid >> 5] = s2; }
    __syncthreads();
    if (tid < 8) { s = rs[tid]; s2 = rs2[tid]; } else { s = 0.f; s2 = 0.f; }
    if (tid < 32) {
        for (int off = 4; off > 0; off >>= 1) {
            s  += __shfl_down_sync(0xffffffffu, s,  off);
            s2 += __shfl_down_sync(0xffffffffu, s2, off);
        }
        if (tid == 0) { rs[0] = s; rs2[0] = s2; }
    }
    __syncthreads();
    const float mean = rs[0] * (1.0f / DD);
    const float var  = rs2[0] * (1.0f / DD) - mean * mean;
    const float inv  = rsqrtf(var + 1e-5f);
    __half* yr = y + (size_t)row * DD;
#pragma unroll
    for (int i = 0; i < 4; ++i) {
        const int c = tid + i * 256;
        yr[c] = __float2half_rn((v[i] - mean) * inv * g[c] + b[c]);
    }
}

// ---------------- weight transpose: w[K,N] fp32 -> [N,K] fp16 -------------------
__global__ void wsplit_kernel(const float* __restrict__ w,
                              __half* __restrict__ bh, int K, int N) {
    __shared__ float t[32][33];
    const int bx = blockIdx.x;   // n tile
    const int by = blockIdx.y;   // k tile
    const int tx = threadIdx.x & 31;
    const int ty = threadIdx.x >> 5;   // 0..7
#pragma unroll
    for (int i = 0; i < 32; i += 8)
        t[ty + i][tx] = w[(size_t)(by * 32 + ty + i) * N + bx * 32 + tx];
    __syncthreads();
#pragma unroll
    for (int i = 0; i < 32; i += 8) {
        const int n = bx * 32 + ty + i;
        const int k = by * 32 + tx;
        bh[(size_t)n * K + k] = __float2half_rn(t[tx][ty + i]);
    }
}

// ---------------- fp16 GEMM: C[M,N] = A[M,K] @ B^T ([N,K] fp16) -----------------
// Single-term fp16 x fp16, fp32 accumulate.
// CTA tile 128x128, BK=32, 8 warps (4x2), warp tile 32x64, double buffer.
#define ROWB 80
#define TILESZ (128*ROWB)      // 10240
#define BUF2   (2*TILESZ)      // A, B = 20480
#define GEMM_SMEM (2*BUF2 + 512)

__device__ __forceinline__ void issue_chunk2(const __half* const* tp, int k0,
                                             uint32_t buf, int tid, int K) {
#pragma unroll
    for (int t = 0; t < 2; ++t) {
#pragma unroll
        for (int u = 0; u < 2; ++u) {
            const int lin = tid + u * 256;       // 0..511
            const int r = lin >> 2;              // 0..127
            const int c4 = lin & 3;              // 16B chunk
            const void* src = tp[t] + (size_t)r * K + k0 + c4 * 8;
            cp_async16(buf + t * TILESZ + r * ROWB + c4 * 16, src);
        }
    }
    cp_commit();
}

template<int OUTMODE /*0=f32, 2=fp16*/, bool HAS_RES, bool DO_GELU>
__global__ void __launch_bounds__(256)
tc_gemm(const __half* __restrict__ A, const __half* __restrict__ B,
        const float* __restrict__ bias, const float* __restrict__ res,
        float* __restrict__ Cf, __half* __restrict__ Ch,
        int M, int N, int K) {
    extern __shared__ char smem[];
    const uint32_t sbase = smem_u32(smem);
    float* bias_s = (float*)(smem + 2 * BUF2);

    const int tid  = threadIdx.x;
    const int wid  = tid >> 5;
    const int lane = tid & 31;
    const int wm = wid >> 1;
    const int wn = wid & 1;
    const int bx = blockIdx.x, by = blockIdx.y;

    if (tid < 128) bias_s[tid] = bias[bx * 128 + tid];

    const size_t aoff = (size_t)by * 128 * K;
    const size_t boff = (size_t)bx * 128 * K;
    const __half* tp[2] = { A + aoff, B + boff };

    const int nchunk = K >> 5;

    float acc[2][8][4];
#pragma unroll
    for (int mt = 0; mt < 2; ++mt)
#pragma unroll
        for (int nt = 0; nt < 8; ++nt)
#pragma unroll
            for (int e = 0; e < 4; ++e) acc[mt][nt][e] = 0.f;

    const int a_row = wm * 32 + (lane & 15);
    const int a_kof = (lane >> 4) << 3;
    const int b_row = wn * 64 + (lane & 7) + ((lane >> 4) << 3);
    const int b_kof = ((lane >> 3) & 1) << 3;

    issue_chunk2(tp, 0, sbase, tid, K);

    for (int i = 0; i < nchunk; ++i) {
        if (i + 1 < nchunk)
            issue_chunk2(tp, (i + 1) << 5, sbase + ((i + 1) & 1) * BUF2, tid, K);
        if (i + 1 < nchunk) cp_wait<1>(); else cp_wait<0>();
        __syncthreads();

        const uint32_t buf = sbase + (i & 1) * BUF2;
        const uint32_t aA = buf + a_row * ROWB;
        const uint32_t aB = buf + TILESZ + b_row * ROWB;

#pragma unroll
        for (int ks = 0; ks < 2; ++ks) {
            const int ak = (ks * 16 + a_kof) * 2;
            const int bk = (ks * 16 + b_kof) * 2;
            uint32_t ah[2][4], bh[8][2];
#pragma unroll
            for (int mt = 0; mt < 2; ++mt)
                ldsm_x4(ah[mt], aA + mt * 16 * ROWB + ak);
#pragma unroll
            for (int p = 0; p < 4; ++p) {
                uint32_t r[4];
                ldsm_x4(r, aB + p * 16 * ROWB + bk);
                bh[2*p][0] = r[0]; bh[2*p][1] = r[1];
                bh[2*p+1][0] = r[2]; bh[2*p+1][1] = r[3];
            }
#pragma unroll
            for (int mt = 0; mt < 2; ++mt)
#pragma unroll
                for (int nt = 0; nt < 8; ++nt)
                    mma16816h(acc[mt][nt], ah[mt], bh[nt]);
        }
        __syncthreads();
    }

    const int mbase = by * 128 + wm * 32;
    const int nloc0 = wn * 64;
#pragma unroll
    for (int mt = 0; mt < 2; ++mt) {
#pragma unroll
        for (int half = 0; half < 2; ++half) {
            const int m = mbase + mt * 16 + (lane >> 2) + half * 8;
#pragma unroll
            for (int nt = 0; nt < 8; ++nt) {
                const int nloc = nloc0 + nt * 8 + 2 * (lane & 3);
                const int n = bx * 128 + nloc;
                float v0 = acc[mt][nt][half * 2 + 0] + bias_s[nloc];
                float v1 = acc[mt][nt][half * 2 + 1] + bias_s[nloc + 1];
                if (DO_GELU) {
                    v0 = 0.5f * v0 * (1.0f + erff(v0 * 0.70710678118654752f));
                    v1 = 0.5f * v1 * (1.0f + erff(v1 * 0.70710678118654752f));
                }
                if (HAS_RES) {
                    const float2 rv = *(const float2*)(res + (size_t)m * N + n);
                    v0 += rv.x; v1 += rv.y;
                }
                if (OUTMODE == 0) {
                    *(float2*)(Cf + (size_t)m * N + n) = make_float2(v0, v1);
                } else {
                    *(__half2*)(Ch + (size_t)m * N + n) = __floats2half2_rn(v0, v1);
                }
            }
        }
    }
}

// ---------------- Flash attention via mma.sync (fp16 single-term, causal) -------
// CTA: 128 q-rows x DH=64, 8 warps. K-tiles of 64 keys. O written as fp16.
#define AROWB 144
#define ATT_SMEM (AROWB*(128 + 64 + 64))   // Q + K + V = 36864

__global__ void __launch_bounds__(256, 2)
attn_mma(const __half* __restrict__ q, const __half* __restrict__ k,
         const __half* __restrict__ v, __half* __restrict__ o) {
    extern __shared__ char sm[];
    const uint32_t sb = smem_u32(sm);
    const uint32_t sQ = sb;
    const uint32_t sK = sb + 128 * AROWB;
    const uint32_t sV = sK + 64 * AROWB;

    const int qt = gridDim.x - 1 - blockIdx.x;   // big tiles first
    const int bh = blockIdx.y;
    const int b = bh >> 4, h = bh & 15;
    const size_t base = (size_t)b * SS * DD + (size_t)h * DHH;
    const int q0 = qt * 128;

    const int tid = threadIdx.x, warp = tid >> 5, lane = tid & 31;

    // stage Q
#pragma unroll
    for (int u = 0; u < 4; ++u) {
        const int lin = tid + u * 256;       // 0..1023
        const int r = lin >> 3, c = lin & 7;
        cp_async16(sQ + r * AROWB + c * 16, q + base + (size_t)(q0 + r) * DD + c * 8);
    }
    cp_commit();

    float sfr[8][4], oac[8][4];
    float m0 = -1e30f, m1 = -1e30f, l0 = 0.f, l1 = 0.f;
#pragma unroll
    for (int j = 0; j < 8; ++j)
#pragma unroll
        for (int e = 0; e < 4; ++e) oac[j][e] = 0.f;

    const uint32_t qb = sQ + (warp * 16 + (lane & 15)) * AROWB + (((lane >> 4) << 3) << 1);
    const int krow = (lane & 7) + ((lane >> 4) << 3);
    const uint32_t kof = (((lane >> 3) & 1) << 3) << 1;
    const int vrow = lane & 15;
    const uint32_t vof = (((lane >> 4) << 3)) << 1;

    cp_wait<0>();
    __syncthreads();

    const int ntile = qt * 2 + 2;
    for (int kt = 0; kt < ntile; ++kt) {
        const int k0 = kt * 64;
        __syncthreads();
        {
            const __half* srck = k + base + (size_t)k0 * DD;
            const __half* srcv = v + base + (size_t)k0 * DD;
#pragma unroll
            for (int u = 0; u < 2; ++u) {
                const int lin = tid + u * 256;   // 0..511 -> 64 rows x 8 chunks
                const int rr = lin >> 3, cc = lin & 7;
                const size_t go = (size_t)rr * DD + cc * 8;
                const uint32_t so = rr * AROWB + cc * 16;
                cp_async16(sK + so, srck + go);
                cp_async16(sV + so, srcv + go);
            }
            cp_commit(); cp_wait<0>();
            __syncthreads();
        }

        // ---- scores S = Q @ K^T ----
#pragma unroll
        for (int j = 0; j < 8; ++j)
#pragma unroll
            for (int e = 0; e < 4; ++e) sfr[j][e] = 0.f;
#pragma unroll
        for (int t = 0; t < 4; ++t) {
            uint32_t qa[4];
            ldsm_x4(qa, qb + t * 32);
#pragma unroll
            for (int g = 0; g < 4; ++g) {
                uint32_t kb[4];
                ldsm_x4(kb, sK + (g * 16 + krow) * AROWB + t * 32 + kof);
                mma16816h(sfr[2*g],   qa, kb);
                mma16816h(sfr[2*g+1], qa, kb + 2);
            }
        }

        // ---- online softmax (base-2 domain, warp-local rows) ----
        const float cs = 0.1803368801111204f;   // 0.125 * log2(e)
        const int rg0 = q0 + warp * 16 + (lane >> 2);
        if (kt >= 2 * qt) {
#pragma unroll
            for (int j = 0; j < 8; ++j) {
                const int cb = k0 + j * 8 + 2 * (lane & 3);
#pragma unroll
                for (int e = 0; e < 4; ++e) {
                    const int cg = cb + (e & 1);
                    const int rg = rg0 + ((e >> 1) << 3);
                    const float s = sfr[j][e] * cs;
                    sfr[j][e] = (cg > rg) ? -1e30f : s;
                }
            }
        } else {
#pragma unroll
            for (int j = 0; j < 8; ++j)
#pragma unroll
                for (int e = 0; e < 4; ++e) sfr[j][e] *= cs;
        }
        float mx0 = -1e30f, mx1 = -1e30f;
#pragma unroll
        for (int j = 0; j < 8; ++j) {
            mx0 = fmaxf(mx0, fmaxf(sfr[j][0], sfr[j][1]));
            mx1 = fmaxf(mx1, fmaxf(sfr[j][2], sfr[j][3]));
        }
        mx0 = fmaxf(mx0, __shfl_xor_sync(0xffffffffu, mx0, 1));
        mx0 = fmaxf(mx0, __shfl_xor_sync(0xffffffffu, mx0, 2));
        mx1 = fmaxf(mx1, __shfl_xor_sync(0xffffffffu, mx1, 1));
        mx1 = fmaxf(mx1, __shfl_xor_sync(0xffffffffu, mx1, 2));
        mx0 = fmaxf(mx0, m0);
        mx1 = fmaxf(mx1, m1);
        const float al0 = exp2f(m0 - mx0);
        const float al1 = exp2f(m1 - mx1);
        m0 = mx0; m1 = mx1;
        float s0 = 0.f, s1 = 0.f;
#pragma unroll
        for (int j = 0; j < 8; ++j) {
            float p0 = exp2f(sfr[j][0] - mx0);
            float p1 = exp2f(sfr[j][1] - mx0);
            float p2 = exp2f(sfr[j][2] - mx1);
            float p3 = exp2f(sfr[j][3] - mx1);
            sfr[j][0] = p0; sfr[j][1] = p1; sfr[j][2] = p2; sfr[j][3] = p3;
            s0 += p0 + p1; s1 += p2 + p3;
        }
        s0 += __shfl_xor_sync(0xffffffffu, s0, 1);
        s0 += __shfl_xor_sync(0xffffffffu, s0, 2);
        s1 += __shfl_xor_sync(0xffffffffu, s1, 1);
        s1 += __shfl_xor_sync(0xffffffffu, s1, 2);
        l0 = l0 * al0 + s0;
        l1 = l1 * al1 + s1;
#pragma unroll
        for (int j = 0; j < 8; ++j) {
            oac[j][0] *= al0; oac[j][1] *= al0;
            oac[j][2] *= al1; oac[j][3] *= al1;
        }

        // ---- O += P @ V ----
#pragma unroll
        for (int t = 0; t < 4; ++t) {
            const float* f0 = sfr[2*t];
            const float* f1 = sfr[2*t+1];
            uint32_t pa[4];
            pa[0] = packh(f0[0], f0[1]);
            pa[1] = packh(f0[2], f0[3]);
            pa[2] = packh(f1[0], f1[1]);
            pa[3] = packh(f1[2], f1[3]);
#pragma unroll
            for (int np = 0; np < 4; ++np) {
                uint32_t vb[4];
                ldsm_x4_t(vb, sV + (t * 16 + vrow) * AROWB + np * 32 + vof);
                mma16816h(oac[2*np],   pa, vb);
                mma16816h(oac[2*np+1], pa, vb + 2);
            }
        }
    }

    // ---- write O (fp16) ----
    const float inv0 = 1.f / l0, inv1 = 1.f / l1;
    const int r0g = q0 + warp * 16 + (lane >> 2);
#pragma unroll
    for (int j = 0; j < 8; ++j) {
        const size_t off0 = base + (size_t)r0g * DD + j * 8 + 2 * (lane & 3);
        const size_t off1 = off0 + (size_t)8 * DD;
        *(__half2*)(o + off0) = __floats2half2_rn(oac[j][0] * inv0, oac[j][1] * inv0);
        *(__half2*)(o + off1) = __floats2half2_rn(oac[j][2] * inv1, oac[j][3] * inv1);
    }
}

// ---------------- host launcher -------------------------------------------------
extern "C" void kernel_launch(void* const* d_in, const int* in_sizes, int n_in,
                              void* d_out, int out_size) {
    const float* x     = (const float*)d_in[0];
    const float* ln1_g = (const float*)d_in[1];
    const float* ln1_b = (const float*)d_in[2];
    const float* wq    = (const float*)d_in[3];
    const float* bq    = (const float*)d_in[4];
    const float* wk    = (const float*)d_in[5];
    const float* bk    = (const float*)d_in[6];
    const float* wv    = (const float*)d_in[7];
    const float* bv    = (const float*)d_in[8];
    const float* wo    = (const float*)d_in[9];
    const float* bo    = (const float*)d_in[10];
    const float* ln2_g = (const float*)d_in[11];
    const float* ln2_b = (const float*)d_in[12];
    const float* w1    = (const float*)d_in[13];
    const float* b1    = (const float*)d_in[14];
    const float* w2    = (const float*)d_in[15];
    const float* b2    = (const float*)d_in[16];
    float* out = (float*)d_out;

    __half *ph, *pq, *pk, *pv, *po, *ph2, *pact;
    __half *pwq, *pwk, *pwv, *pwo, *pw1, *pw2;
    float *padd1;
    cudaGetSymbolAddress((void**)&ph,   g_h);
    cudaGetSymbolAddress((void**)&pq,   g_q);
    cudaGetSymbolAddress((void**)&pk,   g_k);
    cudaGetSymbolAddress((void**)&pv,   g_v);
    cudaGetSymbolAddress((void**)&po,   g_o);
    cudaGetSymbolAddress((void**)&padd1,g_add1);
    cudaGetSymbolAddress((void**)&ph2,  g_h2);
    cudaGetSymbolAddress((void**)&pact, g_act);
    cudaGetSymbolAddress((void**)&pwq,  g_wq);    cudaGetSymbolAddress((void**)&pwk,  g_wk);
    cudaGetSymbolAddress((void**)&pwv,  g_wv);    cudaGetSymbolAddress((void**)&pwo,  g_wo);
    cudaGetSymbolAddress((void**)&pw1,  g_w1);    cudaGetSymbolAddress((void**)&pw2,  g_w2);

    cudaFuncSetAttribute(tc_gemm<2,false,false>, cudaFuncAttributeMaxDynamicSharedMemorySize, GEMM_SMEM);
    cudaFuncSetAttribute(tc_gemm<0,true, false>, cudaFuncAttributeMaxDynamicSharedMemorySize, GEMM_SMEM);
    cudaFuncSetAttribute(tc_gemm<2,false,true >, cudaFuncAttributeMaxDynamicSharedMemorySize, GEMM_SMEM);
    cudaFuncSetAttribute(attn_mma, cudaFuncAttributeMaxDynamicSharedMemorySize, ATT_SMEM);

    dim3 gridD(DD/128, NTOK/128);
    dim3 gridF(FF/128, NTOK/128);

    // #1 ln1 -> fp16
    ln_half_kernel<<<NTOK, 256>>>(x, ln1_g, ln1_b, ph);
    // #2, #3 weight transposes for Q, K
    wsplit_kernel<<<dim3(DD/32, DD/32), 256>>>(wq, pwq, DD, DD);
    wsplit_kernel<<<dim3(DD/32, DD/32), 256>>>(wk, pwk, DD, DD);
    // #4 (ncu-profiled slot): Q projection GEMM
    tc_gemm<2,false,false><<<gridD, 256, GEMM_SMEM>>>(ph, pwq, bq, nullptr, nullptr, pq, NTOK, DD, DD);
    // #5 wv split, #6 K GEMM, #7 V GEMM
    wsplit_kernel<<<dim3(DD/32, DD/32), 256>>>(wv, pwv, DD, DD);
    tc_gemm<2,false,false><<<gridD, 256, GEMM_SMEM>>>(ph, pwk, bk, nullptr, nullptr, pk, NTOK, DD, DD);
    tc_gemm<2,false,false><<<gridD, 256, GEMM_SMEM>>>(ph, pwv, bv, nullptr, nullptr, pv, NTOK, DD, DD);

    // #8 attention
    {
        dim3 grid(SS/128, BB*HH);
        attn_mma<<<grid, 256, ATT_SMEM>>>(pq, pk, pv, po);
    }

    // #9 wo split, #10 O-proj + residual: add1 = x + o@wo + bo
    wsplit_kernel<<<dim3(DD/32, DD/32), 256>>>(wo, pwo, DD, DD);
    tc_gemm<0,true,false><<<gridD, 256, GEMM_SMEM>>>(po, pwo, bo, x, padd1, nullptr, NTOK, DD, DD);

    // #11 ln2, #12 w1 split
    ln_half_kernel<<<NTOK, 256>>>(padd1, ln2_g, ln2_b, ph2);
    wsplit_kernel<<<dim3(FF/32, DD/32), 256>>>(w1, pw1, DD, FF);

    // #13 MLP up + gelu -> fp16
    tc_gemm<2,false,true><<<gridF, 256, GEMM_SMEM>>>(ph2, pw1, b1, nullptr, nullptr, pact, NTOK, FF, DD);

    // #14 w2 split, #15 MLP down + residual -> out
    wsplit_kernel<<<dim3(DD/32, FF/32), 256>>>(w2, pw2, FF, DD);
    tc_gemm<0,true,false><<<gridD, 256, GEMM_SMEM>>>(pact, pw2, b2, padd1, out, nullptr, NTOK, DD, FF);
}